// round 3
// baseline (speedup 1.0000x reference)
#include <cuda_runtime.h>

#define NB 8192
#define NSPLIT 8
#define JCHUNK (NB / NSPLIT)
#define WIDTH 64
#define SAMPLES_PER_BLK 8
#define THREADS (SAMPLES_PER_BLK * WIDTH)
#define STEPS 50
#define LR 0.1f

// scratch (no allocations allowed)
__device__ float g_nnd[NSPLIT * NB];
__device__ int   g_nnj[NSPLIT * NB];
__device__ float g_c0[NB];

// ---------------------------------------------------------------------------
// Nearest neighbor (1-D c, brute force, split over j for parallelism).
// Reference: dists = |ci - cj| (+1e9 on diag), argmin (first-min index).
// Comparing squared distances preserves ordering; strict-< ascending scan
// reproduces argmin's first-index tie-break.
// ---------------------------------------------------------------------------
__global__ void nn_partial(const float* __restrict__ c) {
    __shared__ float sc[JCHUNK];
    const int i = blockIdx.x * blockDim.x + threadIdx.x;
    const int q = blockIdx.y;
    const int jbase = q * JCHUNK;
    for (int t = threadIdx.x; t < JCHUNK; t += blockDim.x)
        sc[t] = c[jbase + t];
    __syncthreads();
    const float ci = c[i];
    float best = 1e30f;
    int bj = jbase;
    #pragma unroll 4
    for (int jj = 0; jj < JCHUNK; ++jj) {
        const int j = jbase + jj;
        float d = sc[jj] - ci;
        d = d * d;
        if (j != i && d < best) { best = d; bj = j; }
    }
    g_nnd[q * NB + i] = best;
    g_nnj[q * NB + i] = bj;
}

__global__ void nn_combine(const float* __restrict__ c) {
    const int i = blockIdx.x * blockDim.x + threadIdx.x;
    float best = 1e30f;
    int bj = 0;
    #pragma unroll
    for (int q = 0; q < NSPLIT; ++q) {
        const float d = g_nnd[q * NB + i];
        if (d < best) { best = d; bj = g_nnj[q * NB + i]; }
    }
    g_c0[i] = c[bj];
}

// ---------------------------------------------------------------------------
// Persistent inner-loop solver.
// Per sample: y <- y - 0.1 * dE/dy(x, y, c0), 50 steps.
// Forward-mode jet (v, dy) through the 3-hidden-layer ReLU MLP.
// Thread (s, n): sample s (local), neuron n. Weights W2^T/W3^T in shared.
// ---------------------------------------------------------------------------
__global__ __launch_bounds__(THREADS) void taylor_solve(
    const float* __restrict__ x,
    const float* __restrict__ W1, const float* __restrict__ b1,
    const float* __restrict__ W2, const float* __restrict__ b2,
    const float* __restrict__ W3, const float* __restrict__ b3,
    const float* __restrict__ W4,
    float* __restrict__ out)
{
    __shared__ float  sW2T[WIDTH * WIDTH];   // [k][n]
    __shared__ float  sW3T[WIDTH * WIDTH];   // [k][n]
    __shared__ float2 sh1[SAMPLES_PER_BLK][WIDTH];
    __shared__ float2 sh2[SAMPLES_PER_BLK][WIDTH];
    __shared__ float  sred[SAMPLES_PER_BLK][2];

    const int tid = threadIdx.x;
    const int s = tid >> 6;
    const int n = tid & 63;
    const int gs = blockIdx.x * SAMPLES_PER_BLK + s;

    // cooperative transpose loads: sWT[k*64+n] = W[n*64+k]
    for (int t = tid; t < WIDTH * WIDTH; t += THREADS) {
        const int row = t >> 6;        // n (source row)
        const int col = t & 63;        // k (source col)
        sW2T[col * WIDTH + row] = W2[t];
        sW3T[col * WIDTH + row] = W3[t];
    }

    // per-thread constants
    const float xs   = x[gs];
    const float c0s  = g_c0[gs];
    const float w1yn = W1[n * 3 + 1];
    // a = W1[n][0]*x + W1[n][2]*c0 + b1[n]   (y-independent part of layer-1 preact)
    const float a    = fmaf(W1[n * 3 + 0], xs, fmaf(W1[n * 3 + 2], c0s, b1[n]));
    const float b2n  = b2[n];
    const float b3n  = b3[n];
    const float w4n  = W4[n];

    __syncthreads();

    float y = 0.0f;  // Y_MEAN
    for (int it = 0; it < STEPS; ++it) {
        // layer 1
        const float z1 = fmaf(w1yn, y, a);
        float2 h1;
        if (z1 > 0.0f) { h1.x = z1; h1.y = w1yn; }
        else           { h1.x = 0.0f; h1.y = 0.0f; }
        sh1[s][n] = h1;
        __syncthreads();

        // layer 2
        float av = b2n, ad = 0.0f;
        #pragma unroll
        for (int k = 0; k < WIDTH; ++k) {
            const float  w  = sW2T[k * WIDTH + n];
            const float2 hh = sh1[s][k];
            av = fmaf(w, hh.x, av);
            ad = fmaf(w, hh.y, ad);
        }
        float2 h2;
        if (av > 0.0f) { h2.x = av; h2.y = ad; }
        else           { h2.x = 0.0f; h2.y = 0.0f; }
        sh2[s][n] = h2;
        __syncthreads();

        // layer 3
        av = b3n; ad = 0.0f;
        #pragma unroll
        for (int k = 0; k < WIDTH; ++k) {
            const float  w  = sW3T[k * WIDTH + n];
            const float2 hh = sh2[s][k];
            av = fmaf(w, hh.x, av);
            ad = fmaf(w, hh.y, ad);
        }
        const float hd3 = (av > 0.0f) ? ad : 0.0f;

        // layer 4 derivative + reduce: gy = sum_n W4[n] * hd3[n]
        float p = w4n * hd3;
        #pragma unroll
        for (int o = 16; o > 0; o >>= 1)
            p += __shfl_down_sync(0xffffffffu, p, o);
        if ((n & 31) == 0) sred[s][n >> 5] = p;
        __syncthreads();
        const float gy = sred[s][0] + sred[s][1];

        y = fmaf(-LR, gy, y);
    }

    if (n == 0) out[gs] = y;
}

extern "C" void kernel_launch(void* const* d_in, const int* in_sizes, int n_in,
                              void* d_out, int out_size) {
    const float* x  = (const float*)d_in[0];
    const float* c  = (const float*)d_in[1];
    const float* W1 = (const float*)d_in[2];
    const float* b1 = (const float*)d_in[3];
    const float* W2 = (const float*)d_in[4];
    const float* b2 = (const float*)d_in[5];
    const float* W3 = (const float*)d_in[6];
    const float* b3 = (const float*)d_in[7];
    const float* W4 = (const float*)d_in[8];
    // b4 (d_in[9]) does not affect dE/dy

    nn_partial<<<dim3(NB / 256, NSPLIT), 256>>>(c);
    nn_combine<<<NB / 256, 256>>>(c);
    taylor_solve<<<NB / SAMPLES_PER_BLK, THREADS>>>(
        x, W1, b1, W2, b2, W3, b3, W4, (float*)d_out);
}

// round 12
// speedup vs baseline: 2.0185x; 2.0185x over previous
#include <cuda_runtime.h>

#define NB 8192
#define NSPLIT 8
#define JCHUNK (NB / NSPLIT)
#define WIDTH 64
#define STEPS 50
#define LR 0.1f

#define WARPS_PER_BLK 7
#define SPW 8                               // samples per warp
#define THREADS (WARPS_PER_BLK * 32)
#define SAMPLES_PER_BLK (WARPS_PER_BLK * SPW)
#define NBLOCKS ((NB + SAMPLES_PER_BLK - 1) / SAMPLES_PER_BLK)   // 147

// scratch (no allocations allowed)
__device__ float g_nnd[NSPLIT * NB];
__device__ int   g_nnj[NSPLIT * NB];
__device__ float g_c0[NB];

// ---------------------------------------------------------------------------
// packed f32x2 helpers (Blackwell fma.rn.f32x2)
// ---------------------------------------------------------------------------
__device__ __forceinline__ unsigned long long pk2(float a, float b) {
    unsigned long long r;
    asm("mov.b64 %0, {%1, %2};" : "=l"(r) : "f"(a), "f"(b));
    return r;
}
__device__ __forceinline__ void upk2(unsigned long long v, float& a, float& b) {
    asm("mov.b64 {%0, %1}, %2;" : "=f"(a), "=f"(b) : "l"(v));
}
#define FMA2(acc, ww, hh) \
    asm("fma.rn.f32x2 %0, %1, %2, %0;" : "+l"(acc) : "l"(ww), "l"(hh))

// ---------------------------------------------------------------------------
// Nearest neighbor (1-D c, brute force, split over j).
// Reference: dists = |ci - cj| (+1e9 on diag), argmin (first-min index).
// ---------------------------------------------------------------------------
__global__ void nn_partial(const float* __restrict__ c) {
    __shared__ float sc[JCHUNK];
    const int i = blockIdx.x * blockDim.x + threadIdx.x;
    const int q = blockIdx.y;
    const int jbase = q * JCHUNK;
    for (int t = threadIdx.x; t < JCHUNK; t += blockDim.x)
        sc[t] = c[jbase + t];
    __syncthreads();
    const float ci = c[i];
    float best = 1e30f;
    int bj = jbase;
    #pragma unroll 4
    for (int jj = 0; jj < JCHUNK; ++jj) {
        const int j = jbase + jj;
        float d = sc[jj] - ci;
        d = d * d;
        if (j != i && d < best) { best = d; bj = j; }
    }
    g_nnd[q * NB + i] = best;
    g_nnj[q * NB + i] = bj;
}

__global__ void nn_combine(const float* __restrict__ c) {
    const int i = blockIdx.x * blockDim.x + threadIdx.x;
    float best = 1e30f;
    int bj = 0;
    #pragma unroll
    for (int q = 0; q < NSPLIT; ++q) {
        const float d = g_nnd[q * NB + i];
        if (d < best) { best = d; bj = g_nnj[q * NB + i]; }
    }
    g_c0[i] = c[bj];
}

// ---------------------------------------------------------------------------
// Warp-per-8-samples solver. Lane l owns neurons l and l+32 for its warp's
// 8 samples. Jet (value, d/dy) packed in f32x2. No block barriers in the
// 50-step loop; h handoff through a private per-warp smem slice (+syncwarp).
//
// dyn smem layout (float2 units):
//   [0,            2048)  W2p[k][l] = (W2[l][k], W2[l+32][k])
//   [2048,         4096)  W3p same
//   [4096 + w*512, +512)  sh[k][ss]  (64 k-rows x 8 samples, float2 jet)
// ---------------------------------------------------------------------------
__global__ __launch_bounds__(THREADS) void taylor_solve(
    const float* __restrict__ x,
    const float* __restrict__ W1, const float* __restrict__ b1,
    const float* __restrict__ W2, const float* __restrict__ b2,
    const float* __restrict__ W3, const float* __restrict__ b3,
    const float* __restrict__ W4,
    float* __restrict__ out)
{
    extern __shared__ float2 dsm[];
    float2* W2p = dsm;
    float2* W3p = dsm + 2048;

    const int tid = threadIdx.x;
    const int w = tid >> 5;
    const int l = tid & 31;
    float2* sh = dsm + 4096 + w * (WIDTH * SPW);   // [k][ss]

    // cooperative pair-transpose of W2, W3 into smem
    for (int t = tid; t < WIDTH * 32; t += THREADS) {
        const int k = t >> 5;
        const int n = t & 31;
        W2p[t] = make_float2(W2[n * WIDTH + k], W2[(n + 32) * WIDTH + k]);
        W3p[t] = make_float2(W3[n * WIDTH + k], W3[(n + 32) * WIDTH + k]);
    }

    // per-thread constants: neurons nlo = l, nhi = l + 32
    const int nlo = l, nhi = l + 32;
    const float w1y_lo = W1[nlo * 3 + 1];
    const float w1y_hi = W1[nhi * 3 + 1];
    const float b2lo = b2[nlo], b2hi = b2[nhi];
    const float b3lo = b3[nlo], b3hi = b3[nhi];
    const float w4lo = W4[nlo], w4hi = W4[nhi];

    const int gbase = (blockIdx.x * WARPS_PER_BLK + w) * SPW;
    float a_lo[SPW], a_hi[SPW], y[SPW];
    #pragma unroll
    for (int ss = 0; ss < SPW; ++ss) {
        int gs = gbase + ss;
        if (gs >= NB) gs = NB - 1;           // clamp (duplicate work, discarded)
        const float xs = x[gs];
        const float c0s = g_c0[gs];
        a_lo[ss] = fmaf(W1[nlo * 3 + 0], xs, fmaf(W1[nlo * 3 + 2], c0s, b1[nlo]));
        a_hi[ss] = fmaf(W1[nhi * 3 + 0], xs, fmaf(W1[nhi * 3 + 2], c0s, b1[nhi]));
        y[ss] = 0.0f;                         // Y_MEAN
    }

    __syncthreads();   // weights ready

    for (int it = 0; it < STEPS; ++it) {
        // ---- layer 1: jets into sh rows k=l and k=l+32 ----
        #pragma unroll
        for (int ss = 0; ss < SPW; ++ss) {
            const float zlo = fmaf(w1y_lo, y[ss], a_lo[ss]);
            const float zhi = fmaf(w1y_hi, y[ss], a_hi[ss]);
            sh[nlo * SPW + ss] = (zlo > 0.0f) ? make_float2(zlo, w1y_lo)
                                              : make_float2(0.0f, 0.0f);
            sh[nhi * SPW + ss] = (zhi > 0.0f) ? make_float2(zhi, w1y_hi)
                                              : make_float2(0.0f, 0.0f);
        }
        __syncwarp();

        // ---- layer 2 ----
        unsigned long long acc_l[SPW], acc_h[SPW];
        #pragma unroll
        for (int ss = 0; ss < SPW; ++ss) {
            acc_l[ss] = pk2(b2lo, 0.0f);
            acc_h[ss] = pk2(b2hi, 0.0f);
        }
        #pragma unroll
        for (int k = 0; k < WIDTH; ++k) {
            const float2 wp = W2p[k * 32 + l];
            const unsigned long long wwl = pk2(wp.x, wp.x);
            const unsigned long long wwh = pk2(wp.y, wp.y);
            const ulonglong2* hv = reinterpret_cast<const ulonglong2*>(sh + k * SPW);
            const ulonglong2 h01 = hv[0], h23 = hv[1], h45 = hv[2], h67 = hv[3];
            FMA2(acc_l[0], wwl, h01.x); FMA2(acc_h[0], wwh, h01.x);
            FMA2(acc_l[1], wwl, h01.y); FMA2(acc_h[1], wwh, h01.y);
            FMA2(acc_l[2], wwl, h23.x); FMA2(acc_h[2], wwh, h23.x);
            FMA2(acc_l[3], wwl, h23.y); FMA2(acc_h[3], wwh, h23.y);
            FMA2(acc_l[4], wwl, h45.x); FMA2(acc_h[4], wwh, h45.x);
            FMA2(acc_l[5], wwl, h45.y); FMA2(acc_h[5], wwh, h45.y);
            FMA2(acc_l[6], wwl, h67.x); FMA2(acc_h[6], wwh, h67.x);
            FMA2(acc_l[7], wwl, h67.y); FMA2(acc_h[7], wwh, h67.y);
        }
        __syncwarp();   // all lanes finished reading h1 before overwrite
        #pragma unroll
        for (int ss = 0; ss < SPW; ++ss) {
            float zv, zd;
            upk2(acc_l[ss], zv, zd);
            sh[nlo * SPW + ss] = (zv > 0.0f) ? make_float2(zv, zd)
                                             : make_float2(0.0f, 0.0f);
            upk2(acc_h[ss], zv, zd);
            sh[nhi * SPW + ss] = (zv > 0.0f) ? make_float2(zv, zd)
                                             : make_float2(0.0f, 0.0f);
        }
        __syncwarp();

        // ---- layer 3 ----
        #pragma unroll
        for (int ss = 0; ss < SPW; ++ss) {
            acc_l[ss] = pk2(b3lo, 0.0f);
            acc_h[ss] = pk2(b3hi, 0.0f);
        }
        #pragma unroll
        for (int k = 0; k < WIDTH; ++k) {
            const float2 wp = W3p[k * 32 + l];
            const unsigned long long wwl = pk2(wp.x, wp.x);
            const unsigned long long wwh = pk2(wp.y, wp.y);
            const ulonglong2* hv = reinterpret_cast<const ulonglong2*>(sh + k * SPW);
            const ulonglong2 h01 = hv[0], h23 = hv[1], h45 = hv[2], h67 = hv[3];
            FMA2(acc_l[0], wwl, h01.x); FMA2(acc_h[0], wwh, h01.x);
            FMA2(acc_l[1], wwl, h01.y); FMA2(acc_h[1], wwh, h01.y);
            FMA2(acc_l[2], wwl, h23.x); FMA2(acc_h[2], wwh, h23.x);
            FMA2(acc_l[3], wwl, h23.y); FMA2(acc_h[3], wwh, h23.y);
            FMA2(acc_l[4], wwl, h45.x); FMA2(acc_h[4], wwh, h45.x);
            FMA2(acc_l[5], wwl, h45.y); FMA2(acc_h[5], wwh, h45.y);
            FMA2(acc_l[6], wwl, h67.x); FMA2(acc_h[6], wwh, h67.x);
            FMA2(acc_l[7], wwl, h67.y); FMA2(acc_h[7], wwh, h67.y);
        }

        // ---- layer 4 derivative + warp butterfly reduce + y update ----
        #pragma unroll
        for (int ss = 0; ss < SPW; ++ss) {
            float zv, zd, p;
            upk2(acc_l[ss], zv, zd);
            const float dlo = (zv > 0.0f) ? zd : 0.0f;
            upk2(acc_h[ss], zv, zd);
            const float dhi = (zv > 0.0f) ? zd : 0.0f;
            p = fmaf(w4lo, dlo, w4hi * dhi);
            #pragma unroll
            for (int o = 16; o > 0; o >>= 1)
                p += __shfl_xor_sync(0xffffffffu, p, o);
            y[ss] = fmaf(-LR, p, y[ss]);
        }
        __syncwarp();   // h overwrite next step must wait for layer-3 reads
    }

    if (l == 0) {
        #pragma unroll
        for (int ss = 0; ss < SPW; ++ss) {
            const int gs = gbase + ss;
            if (gs < NB) out[gs] = y[ss];
        }
    }
}

extern "C" void kernel_launch(void* const* d_in, const int* in_sizes, int n_in,
                              void* d_out, int out_size) {
    const float* x  = (const float*)d_in[0];
    const float* c  = (const float*)d_in[1];
    const float* W1 = (const float*)d_in[2];
    const float* b1 = (const float*)d_in[3];
    const float* W2 = (const float*)d_in[4];
    const float* b2 = (const float*)d_in[5];
    const float* W3 = (const float*)d_in[6];
    const float* b3 = (const float*)d_in[7];
    const float* W4 = (const float*)d_in[8];
    // b4 (d_in[9]) does not affect dE/dy

    const int smem = (4096 + WARPS_PER_BLK * WIDTH * SPW) * (int)sizeof(float2); // 60KB
    static int attr_done = 0;
    if (!attr_done) {
        cudaFuncSetAttribute(taylor_solve,
                             cudaFuncAttributeMaxDynamicSharedMemorySize, smem);
        attr_done = 1;
    }

    nn_partial<<<dim3(NB / 256, NSPLIT), 256>>>(c);
    nn_combine<<<NB / 256, 256>>>(c);
    taylor_solve<<<NBLOCKS, THREADS, smem>>>(
        x, W1, b1, W2, b2, W3, b3, W4, (float*)d_out);
}

// round 16
// speedup vs baseline: 2.2529x; 1.1162x over previous
#include <cuda_runtime.h>

#define NB 8192
#define NSPLIT 8
#define JCHUNK (NB / NSPLIT)
#define WIDTH 64
#define STEPS 50
#define LR 0.1f

#define WARPS_PER_BLK 14
#define SPW 4                               // samples per warp
#define THREADS (WARPS_PER_BLK * 32)
#define SAMPLES_PER_BLK (WARPS_PER_BLK * SPW)
#define NBLOCKS ((NB + SAMPLES_PER_BLK - 1) / SAMPLES_PER_BLK)   // 147

// scratch (no allocations allowed)
__device__ float g_nnd[NSPLIT * NB];
__device__ int   g_nnj[NSPLIT * NB];
__device__ float g_c0[NB];

// ---------------------------------------------------------------------------
// packed f32x2 helpers (Blackwell fma.rn.f32x2)
// ---------------------------------------------------------------------------
__device__ __forceinline__ unsigned long long pk2(float a, float b) {
    unsigned long long r;
    asm("mov.b64 %0, {%1, %2};" : "=l"(r) : "f"(a), "f"(b));
    return r;
}
__device__ __forceinline__ void upk2(unsigned long long v, float& a, float& b) {
    asm("mov.b64 {%0, %1}, %2;" : "=f"(a), "=f"(b) : "l"(v));
}
#define FMA2(acc, ww, hh) \
    asm("fma.rn.f32x2 %0, %1, %2, %0;" : "+l"(acc) : "l"(ww), "l"(hh))

// ---------------------------------------------------------------------------
// Nearest neighbor (1-D c, brute force, split over j).
// Reference: dists = |ci - cj| (+1e9 on diag), argmin (first-min index).
// ---------------------------------------------------------------------------
__global__ void nn_partial(const float* __restrict__ c) {
    __shared__ float sc[JCHUNK];
    const int i = blockIdx.x * blockDim.x + threadIdx.x;
    const int q = blockIdx.y;
    const int jbase = q * JCHUNK;
    for (int t = threadIdx.x; t < JCHUNK; t += blockDim.x)
        sc[t] = c[jbase + t];
    __syncthreads();
    const float ci = c[i];
    float best = 1e30f;
    int bj = jbase;
    #pragma unroll 4
    for (int jj = 0; jj < JCHUNK; ++jj) {
        const int j = jbase + jj;
        float d = sc[jj] - ci;
        d = d * d;
        if (j != i && d < best) { best = d; bj = j; }
    }
    g_nnd[q * NB + i] = best;
    g_nnj[q * NB + i] = bj;
}

__global__ void nn_combine(const float* __restrict__ c) {
    const int i = blockIdx.x * blockDim.x + threadIdx.x;
    float best = 1e30f;
    int bj = 0;
    #pragma unroll
    for (int q = 0; q < NSPLIT; ++q) {
        const float d = g_nnd[q * NB + i];
        if (d < best) { best = d; bj = g_nnj[q * NB + i]; }
    }
    g_c0[i] = c[bj];
}

// ---------------------------------------------------------------------------
// Warp-per-4-samples solver (occupancy A/B vs SPW=8: 14 warps/SM).
// Lane l owns neurons l and l+32 for its warp's 4 samples. Jet (value, d/dy)
// packed in f32x2. No block barriers in the 50-step loop.
//
// dyn smem layout (float2 units):
//   [0,            2048)  W2p[k][l] = (W2[l][k], W2[l+32][k])
//   [2048,         4096)  W3p same
//   [4096 + w*256, +256)  sh[k][ss]  (64 k-rows x 4 samples, float2 jet)
// ---------------------------------------------------------------------------
__global__ __launch_bounds__(THREADS) void taylor_solve(
    const float* __restrict__ x,
    const float* __restrict__ W1, const float* __restrict__ b1,
    const float* __restrict__ W2, const float* __restrict__ b2,
    const float* __restrict__ W3, const float* __restrict__ b3,
    const float* __restrict__ W4,
    float* __restrict__ out)
{
    extern __shared__ float2 dsm[];
    float2* W2p = dsm;
    float2* W3p = dsm + 2048;

    const int tid = threadIdx.x;
    const int w = tid >> 5;
    const int l = tid & 31;
    float2* sh = dsm + 4096 + w * (WIDTH * SPW);   // [k][ss]

    // cooperative pair-transpose of W2, W3 into smem
    for (int t = tid; t < WIDTH * 32; t += THREADS) {
        const int k = t >> 5;
        const int n = t & 31;
        W2p[t] = make_float2(W2[n * WIDTH + k], W2[(n + 32) * WIDTH + k]);
        W3p[t] = make_float2(W3[n * WIDTH + k], W3[(n + 32) * WIDTH + k]);
    }

    // per-thread constants: neurons nlo = l, nhi = l + 32
    const int nlo = l, nhi = l + 32;
    const float w1y_lo = W1[nlo * 3 + 1];
    const float w1y_hi = W1[nhi * 3 + 1];
    const float b2lo = b2[nlo], b2hi = b2[nhi];
    const float b3lo = b3[nlo], b3hi = b3[nhi];
    const float w4lo = W4[nlo], w4hi = W4[nhi];

    const int gbase = (blockIdx.x * WARPS_PER_BLK + w) * SPW;
    float a_lo[SPW], a_hi[SPW], y[SPW];
    #pragma unroll
    for (int ss = 0; ss < SPW; ++ss) {
        int gs = gbase + ss;
        if (gs >= NB) gs = NB - 1;           // clamp (duplicate work, discarded)
        const float xs = x[gs];
        const float c0s = g_c0[gs];
        a_lo[ss] = fmaf(W1[nlo * 3 + 0], xs, fmaf(W1[nlo * 3 + 2], c0s, b1[nlo]));
        a_hi[ss] = fmaf(W1[nhi * 3 + 0], xs, fmaf(W1[nhi * 3 + 2], c0s, b1[nhi]));
        y[ss] = 0.0f;                         // Y_MEAN
    }

    __syncthreads();   // weights ready

    for (int it = 0; it < STEPS; ++it) {
        // ---- layer 1: jets into sh rows k=l and k=l+32 ----
        #pragma unroll
        for (int ss = 0; ss < SPW; ++ss) {
            const float zlo = fmaf(w1y_lo, y[ss], a_lo[ss]);
            const float zhi = fmaf(w1y_hi, y[ss], a_hi[ss]);
            sh[nlo * SPW + ss] = (zlo > 0.0f) ? make_float2(zlo, w1y_lo)
                                              : make_float2(0.0f, 0.0f);
            sh[nhi * SPW + ss] = (zhi > 0.0f) ? make_float2(zhi, w1y_hi)
                                              : make_float2(0.0f, 0.0f);
        }
        __syncwarp();

        // ---- layer 2 ----
        unsigned long long acc_l[SPW], acc_h[SPW];
        #pragma unroll
        for (int ss = 0; ss < SPW; ++ss) {
            acc_l[ss] = pk2(b2lo, 0.0f);
            acc_h[ss] = pk2(b2hi, 0.0f);
        }
        #pragma unroll
        for (int k = 0; k < WIDTH; ++k) {
            const float2 wp = W2p[k * 32 + l];
            const unsigned long long wwl = pk2(wp.x, wp.x);
            const unsigned long long wwh = pk2(wp.y, wp.y);
            const ulonglong2* hv = reinterpret_cast<const ulonglong2*>(sh + k * SPW);
            const ulonglong2 h01 = hv[0], h23 = hv[1];
            FMA2(acc_l[0], wwl, h01.x); FMA2(acc_h[0], wwh, h01.x);
            FMA2(acc_l[1], wwl, h01.y); FMA2(acc_h[1], wwh, h01.y);
            FMA2(acc_l[2], wwl, h23.x); FMA2(acc_h[2], wwh, h23.x);
            FMA2(acc_l[3], wwl, h23.y); FMA2(acc_h[3], wwh, h23.y);
        }
        __syncwarp();   // all lanes finished reading h1 before overwrite
        #pragma unroll
        for (int ss = 0; ss < SPW; ++ss) {
            float zv, zd;
            upk2(acc_l[ss], zv, zd);
            sh[nlo * SPW + ss] = (zv > 0.0f) ? make_float2(zv, zd)
                                             : make_float2(0.0f, 0.0f);
            upk2(acc_h[ss], zv, zd);
            sh[nhi * SPW + ss] = (zv > 0.0f) ? make_float2(zv, zd)
                                             : make_float2(0.0f, 0.0f);
        }
        __syncwarp();

        // ---- layer 3 ----
        #pragma unroll
        for (int ss = 0; ss < SPW; ++ss) {
            acc_l[ss] = pk2(b3lo, 0.0f);
            acc_h[ss] = pk2(b3hi, 0.0f);
        }
        #pragma unroll
        for (int k = 0; k < WIDTH; ++k) {
            const float2 wp = W3p[k * 32 + l];
            const unsigned long long wwl = pk2(wp.x, wp.x);
            const unsigned long long wwh = pk2(wp.y, wp.y);
            const ulonglong2* hv = reinterpret_cast<const ulonglong2*>(sh + k * SPW);
            const ulonglong2 h01 = hv[0], h23 = hv[1];
            FMA2(acc_l[0], wwl, h01.x); FMA2(acc_h[0], wwh, h01.x);
            FMA2(acc_l[1], wwl, h01.y); FMA2(acc_h[1], wwh, h01.y);
            FMA2(acc_l[2], wwl, h23.x); FMA2(acc_h[2], wwh, h23.x);
            FMA2(acc_l[3], wwl, h23.y); FMA2(acc_h[3], wwh, h23.y);
        }

        // ---- layer 4 derivative + warp butterfly reduce + y update ----
        #pragma unroll
        for (int ss = 0; ss < SPW; ++ss) {
            float zv, zd, p;
            upk2(acc_l[ss], zv, zd);
            const float dlo = (zv > 0.0f) ? zd : 0.0f;
            upk2(acc_h[ss], zv, zd);
            const float dhi = (zv > 0.0f) ? zd : 0.0f;
            p = fmaf(w4lo, dlo, w4hi * dhi);
            #pragma unroll
            for (int o = 16; o > 0; o >>= 1)
                p += __shfl_xor_sync(0xffffffffu, p, o);
            y[ss] = fmaf(-LR, p, y[ss]);
        }
        __syncwarp();   // h overwrite next step must wait for layer-3 reads
    }

    if (l == 0) {
        #pragma unroll
        for (int ss = 0; ss < SPW; ++ss) {
            const int gs = gbase + ss;
            if (gs < NB) out[gs] = y[ss];
        }
    }
}

extern "C" void kernel_launch(void* const* d_in, const int* in_sizes, int n_in,
                              void* d_out, int out_size) {
    const float* x  = (const float*)d_in[0];
    const float* c  = (const float*)d_in[1];
    const float* W1 = (const float*)d_in[2];
    const float* b1 = (const float*)d_in[3];
    const float* W2 = (const float*)d_in[4];
    const float* b2 = (const float*)d_in[5];
    const float* W3 = (const float*)d_in[6];
    const float* b3 = (const float*)d_in[7];
    const float* W4 = (const float*)d_in[8];
    // b4 (d_in[9]) does not affect dE/dy

    const int smem = (4096 + WARPS_PER_BLK * WIDTH * SPW) * (int)sizeof(float2); // 60KB
    static int attr_done = 0;
    if (!attr_done) {
        cudaFuncSetAttribute(taylor_solve,
                             cudaFuncAttributeMaxDynamicSharedMemorySize, smem);
        attr_done = 1;
    }

    nn_partial<<<dim3(NB / 256, NSPLIT), 256>>>(c);
    nn_combine<<<NB / 256, 256>>>(c);
    taylor_solve<<<NBLOCKS, THREADS, smem>>>(
        x, W1, b1, W2, b2, W3, b3, W4, (float*)d_out);
}

// round 17
// speedup vs baseline: 3.3863x; 1.5031x over previous
#include <cuda_runtime.h>

#define NB 8192
#define NSPLIT 8
#define JCHUNK (NB / NSPLIT)
#define WIDTH 64
#define STEPS 50
#define LR 0.1f

#define WARPS_PER_BLK 14
#define SPW 4                               // samples per warp
#define THREADS (WARPS_PER_BLK * 32)
#define SAMPLES_PER_BLK (WARPS_PER_BLK * SPW)
#define NBLOCKS ((NB + SAMPLES_PER_BLK - 1) / SAMPLES_PER_BLK)   // 147

// scratch (no allocations allowed)
__device__ float g_nnd[NSPLIT * NB];
__device__ int   g_nnj[NSPLIT * NB];
__device__ float g_c0[NB];

// ---------------------------------------------------------------------------
// packed f32x2 helpers (Blackwell fma.rn.f32x2)
// ---------------------------------------------------------------------------
__device__ __forceinline__ unsigned long long pk2(float a, float b) {
    unsigned long long r;
    asm("mov.b64 %0, {%1, %2};" : "=l"(r) : "f"(a), "f"(b));
    return r;
}
__device__ __forceinline__ void upk2(unsigned long long v, float& a, float& b) {
    asm("mov.b64 {%0, %1}, %2;" : "=f"(a), "=f"(b) : "l"(v));
}
#define FMA2(acc, ww, hh) \
    asm("fma.rn.f32x2 %0, %1, %2, %0;" : "+l"(acc) : "l"(ww), "l"(hh))

// conservative safe-step count for one preact jet (v, d) under per-step dy
// returns #steps for which this neuron's mask provably cannot flip
__device__ __forceinline__ float safe_steps(float v, float d, float dy) {
    const float s = d * dy;                 // per-step preact change
    if (v > 0.0f) {                         // active; flips when v + k*s <= 0
        if (s >= 0.0f) return 1e30f;
        return floorf(__fdividef(v, -s) * 0.999998f);
    } else {                                // inactive; flips when v + k*s > 0
        if (s <= 0.0f) return 1e30f;
        return floorf(__fdividef(-v, s) * 0.999998f);
    }
}

// ---------------------------------------------------------------------------
// Nearest neighbor (1-D c, brute force, split over j).
// ---------------------------------------------------------------------------
__global__ void nn_partial(const float* __restrict__ c) {
    __shared__ float sc[JCHUNK];
    const int i = blockIdx.x * blockDim.x + threadIdx.x;
    const int q = blockIdx.y;
    const int jbase = q * JCHUNK;
    for (int t = threadIdx.x; t < JCHUNK; t += blockDim.x)
        sc[t] = c[jbase + t];
    __syncthreads();
    const float ci = c[i];
    float best = 1e30f;
    int bj = jbase;
    #pragma unroll 4
    for (int jj = 0; jj < JCHUNK; ++jj) {
        const int j = jbase + jj;
        float d = sc[jj] - ci;
        d = d * d;
        if (j != i && d < best) { best = d; bj = j; }
    }
    g_nnd[q * NB + i] = best;
    g_nnj[q * NB + i] = bj;
}

__global__ void nn_combine(const float* __restrict__ c) {
    const int i = blockIdx.x * blockDim.x + threadIdx.x;
    float best = 1e30f;
    int bj = 0;
    #pragma unroll
    for (int q = 0; q < NSPLIT; ++q) {
        const float d = g_nnd[q * NB + i];
        if (d < best) { best = d; bj = g_nnj[q * NB + i]; }
    }
    g_c0[i] = c[bj];
}

// ---------------------------------------------------------------------------
// Region-skipping solver. gy is piecewise-constant in y (ReLU net); one jet
// pass gives gy plus every preact's affine slope, so we bound how many steps
// fit in the current mask region and fast-forward with an exact fma chain.
// Period-2 kink oscillation detected bitwise and resolved by parity.
// ---------------------------------------------------------------------------
__global__ __launch_bounds__(THREADS) void taylor_solve(
    const float* __restrict__ x,
    const float* __restrict__ W1, const float* __restrict__ b1,
    const float* __restrict__ W2, const float* __restrict__ b2,
    const float* __restrict__ W3, const float* __restrict__ b3,
    const float* __restrict__ W4,
    float* __restrict__ out)
{
    extern __shared__ float2 dsm[];
    float2* W2p = dsm;
    float2* W3p = dsm + 2048;

    const int tid = threadIdx.x;
    const int w = tid >> 5;
    const int l = tid & 31;
    float2* sh = dsm + 4096 + w * (WIDTH * SPW);   // [k][ss]

    for (int t = tid; t < WIDTH * 32; t += THREADS) {
        const int k = t >> 5;
        const int n = t & 31;
        W2p[t] = make_float2(W2[n * WIDTH + k], W2[(n + 32) * WIDTH + k]);
        W3p[t] = make_float2(W3[n * WIDTH + k], W3[(n + 32) * WIDTH + k]);
    }

    const int nlo = l, nhi = l + 32;
    const float w1y_lo = W1[nlo * 3 + 1];
    const float w1y_hi = W1[nhi * 3 + 1];
    const float b2lo = b2[nlo], b2hi = b2[nhi];
    const float b3lo = b3[nlo], b3hi = b3[nhi];
    const float w4lo = W4[nlo], w4hi = W4[nhi];

    const int gbase = (blockIdx.x * WARPS_PER_BLK + w) * SPW;
    float a_lo[SPW], a_hi[SPW], y[SPW];
    int   rem[SPW], mh1[SPW];
    float yh1[SPW], yh2[SPW];
    #pragma unroll
    for (int ss = 0; ss < SPW; ++ss) {
        int gs = gbase + ss;
        if (gs >= NB) gs = NB - 1;           // clamp (duplicate work, discarded)
        const float xs = x[gs];
        const float c0s = g_c0[gs];
        a_lo[ss] = fmaf(W1[nlo * 3 + 0], xs, fmaf(W1[nlo * 3 + 2], c0s, b1[nlo]));
        a_hi[ss] = fmaf(W1[nhi * 3 + 0], xs, fmaf(W1[nhi * 3 + 2], c0s, b1[nhi]));
        y[ss] = 0.0f;                         // Y_MEAN
        rem[ss] = STEPS;
        mh1[ss] = 0;
        yh1[ss] = 1e38f; yh2[ss] = -1e38f;    // impossible sentinels
    }

    __syncthreads();   // weights ready

    float z1lo[SPW], z1hi[SPW];
    unsigned long long acc2_l[SPW], acc2_h[SPW], acc3_l[SPW], acc3_h[SPW];

    for (;;) {
        if (!(rem[0] | rem[1] | rem[2] | rem[3])) break;   // lane-uniform

        // ---- layer 1: jets into sh rows k=l and k=l+32 ----
        #pragma unroll
        for (int ss = 0; ss < SPW; ++ss) {
            z1lo[ss] = fmaf(w1y_lo, y[ss], a_lo[ss]);
            z1hi[ss] = fmaf(w1y_hi, y[ss], a_hi[ss]);
            sh[nlo * SPW + ss] = (z1lo[ss] > 0.0f) ? make_float2(z1lo[ss], w1y_lo)
                                                   : make_float2(0.0f, 0.0f);
            sh[nhi * SPW + ss] = (z1hi[ss] > 0.0f) ? make_float2(z1hi[ss], w1y_hi)
                                                   : make_float2(0.0f, 0.0f);
        }
        __syncwarp();

        // ---- layer 2 ----
        #pragma unroll
        for (int ss = 0; ss < SPW; ++ss) {
            acc2_l[ss] = pk2(b2lo, 0.0f);
            acc2_h[ss] = pk2(b2hi, 0.0f);
        }
        #pragma unroll
        for (int k = 0; k < WIDTH; ++k) {
            const float2 wp = W2p[k * 32 + l];
            const unsigned long long wwl = pk2(wp.x, wp.x);
            const unsigned long long wwh = pk2(wp.y, wp.y);
            const ulonglong2* hv = reinterpret_cast<const ulonglong2*>(sh + k * SPW);
            const ulonglong2 h01 = hv[0], h23 = hv[1];
            FMA2(acc2_l[0], wwl, h01.x); FMA2(acc2_h[0], wwh, h01.x);
            FMA2(acc2_l[1], wwl, h01.y); FMA2(acc2_h[1], wwh, h01.y);
            FMA2(acc2_l[2], wwl, h23.x); FMA2(acc2_h[2], wwh, h23.x);
            FMA2(acc2_l[3], wwl, h23.y); FMA2(acc2_h[3], wwh, h23.y);
        }
        __syncwarp();   // all lanes finished reading h1 before overwrite
        #pragma unroll
        for (int ss = 0; ss < SPW; ++ss) {
            float zv, zd;
            upk2(acc2_l[ss], zv, zd);
            sh[nlo * SPW + ss] = (zv > 0.0f) ? make_float2(zv, zd)
                                             : make_float2(0.0f, 0.0f);
            upk2(acc2_h[ss], zv, zd);
            sh[nhi * SPW + ss] = (zv > 0.0f) ? make_float2(zv, zd)
                                             : make_float2(0.0f, 0.0f);
        }
        __syncwarp();

        // ---- layer 3 ----
        #pragma unroll
        for (int ss = 0; ss < SPW; ++ss) {
            acc3_l[ss] = pk2(b3lo, 0.0f);
            acc3_h[ss] = pk2(b3hi, 0.0f);
        }
        #pragma unroll
        for (int k = 0; k < WIDTH; ++k) {
            const float2 wp = W3p[k * 32 + l];
            const unsigned long long wwl = pk2(wp.x, wp.x);
            const unsigned long long wwh = pk2(wp.y, wp.y);
            const ulonglong2* hv = reinterpret_cast<const ulonglong2*>(sh + k * SPW);
            const ulonglong2 h01 = hv[0], h23 = hv[1];
            FMA2(acc3_l[0], wwl, h01.x); FMA2(acc3_h[0], wwh, h01.x);
            FMA2(acc3_l[1], wwl, h01.y); FMA2(acc3_h[1], wwh, h01.y);
            FMA2(acc3_l[2], wwl, h23.x); FMA2(acc3_h[2], wwh, h23.x);
            FMA2(acc3_l[3], wwl, h23.y); FMA2(acc3_h[3], wwh, h23.y);
        }

        // ---- per-sample: gy, region length, fast-forward, cycle detection ----
        #pragma unroll
        for (int ss = 0; ss < SPW; ++ss) {
            if (rem[ss] == 0) continue;       // lane-uniform per sample

            float v3l, d3l, v3h, d3h;
            upk2(acc3_l[ss], v3l, d3l);
            upk2(acc3_h[ss], v3h, d3h);
            const float dlo = (v3l > 0.0f) ? d3l : 0.0f;
            const float dhi = (v3h > 0.0f) ? d3h : 0.0f;
            float gy = fmaf(w4lo, dlo, w4hi * dhi);
            #pragma unroll
            for (int o = 16; o > 0; o >>= 1)
                gy += __shfl_xor_sync(0xffffffffu, gy, o);

            if (gy == 0.0f) {                 // y frozen forever
                rem[ss] = 0;
                continue;
            }
            const float dy = -LR * gy;

            // conservative steps-to-mask-flip over this thread's 6 preacts
            float v2l, d2l, v2h, d2h;
            upk2(acc2_l[ss], v2l, d2l);
            upk2(acc2_h[ss], v2h, d2h);
            float ms = safe_steps(z1lo[ss], w1y_lo, dy);
            ms = fminf(ms, safe_steps(z1hi[ss], w1y_hi, dy));
            ms = fminf(ms, safe_steps(v2l, d2l, dy));
            ms = fminf(ms, safe_steps(v2h, d2h, dy));
            ms = fminf(ms, safe_steps(v3l, d3l, dy));
            ms = fminf(ms, safe_steps(v3h, d3h, dy));
            #pragma unroll
            for (int o = 16; o > 0; o >>= 1)
                ms = fminf(ms, __shfl_xor_sync(0xffffffffu, ms, o));

            int m = (int)fminf(ms, 64.0f) + 1;   // masks valid through state m-1
            if (m > rem[ss]) m = rem[ss];
            if (m < 1) m = 1;

            // exact fma replication (bitwise-identical to reference updates)
            float yy = y[ss];
            for (int i = 0; i < m; ++i) yy = fmaf(-LR, gy, yy);
            int nr = rem[ss] - m;

            // period-2 kink oscillation: state repeats two passes ago
            if (nr > 0 && m == 1 && mh1[ss] == 1 && yy == yh2[ss]) {
                if (nr & 1) yy = yh1[ss];
                nr = 0;
            }
            yh2[ss] = yh1[ss];
            yh1[ss] = yy;
            mh1[ss] = m;
            y[ss] = yy;
            rem[ss] = nr;
        }
        __syncwarp();   // layer-3 reads done before next pass overwrites sh
    }

    if (l == 0) {
        #pragma unroll
        for (int ss = 0; ss < SPW; ++ss) {
            const int gs = gbase + ss;
            if (gs < NB) out[gs] = y[ss];
        }
    }
}

extern "C" void kernel_launch(void* const* d_in, const int* in_sizes, int n_in,
                              void* d_out, int out_size) {
    const float* x  = (const float*)d_in[0];
    const float* c  = (const float*)d_in[1];
    const float* W1 = (const float*)d_in[2];
    const float* b1 = (const float*)d_in[3];
    const float* W2 = (const float*)d_in[4];
    const float* b2 = (const float*)d_in[5];
    const float* W3 = (const float*)d_in[6];
    const float* b3 = (const float*)d_in[7];
    const float* W4 = (const float*)d_in[8];
    // b4 (d_in[9]) does not affect dE/dy

    const int smem = (4096 + WARPS_PER_BLK * WIDTH * SPW) * (int)sizeof(float2); // 60KB
    static int attr_done = 0;
    if (!attr_done) {
        cudaFuncSetAttribute(taylor_solve,
                             cudaFuncAttributeMaxDynamicSharedMemorySize, smem);
        attr_done = 1;
    }

    nn_partial<<<dim3(NB / 256, NSPLIT), 256>>>(c);
    nn_combine<<<NB / 256, 256>>>(c);
    taylor_solve<<<NBLOCKS, THREADS, smem>>>(
        x, W1, b1, W2, b2, W3, b3, W4, (float*)d_out);
}